// round 4
// baseline (speedup 1.0000x reference)
#include <cuda_runtime.h>
#include <math_constants.h>

// Problem constants (from reference)
#define B_    32
#define C_    64
#define H_    64
#define W_    64
#define HW_   (H_*W_)          // 4096
#define CHW_  (C_*HW_)         // 262144
#define NPTS  (B_*HW_)         // 131072 points
#define K_    2048             // codebook entries
#define TPB   128              // threads per block == points per block
#define NBLK  (NPTS/TPB)       // 1024 blocks
#define TK    128              // codes per smem tile

// Scratch (no allocations allowed)
__device__ float g_ee[K_];          // ||e_k||^2
__device__ float g_partials[NBLK];  // per-block loss partial sums

// Packed fp32x2 FMA: two independent IEEE fp32 RN FMAs per issue slot (FFMA2).
__device__ __forceinline__ void ffma2(unsigned long long& acc,
                                      unsigned long long a,
                                      unsigned long long b) {
    asm("fma.rn.f32x2 %0, %1, %2, %0;" : "+l"(acc) : "l"(a), "l"(b));
}
__device__ __forceinline__ void unpack2(unsigned long long v, float& lo, float& hi) {
    asm("mov.b64 {%0, %1}, %2;" : "=f"(lo), "=f"(hi) : "l"(v));
}
__device__ __forceinline__ unsigned long long pack2(float lo, float hi) {
    unsigned long long v;
    asm("mov.b64 %0, {%1, %2};" : "=l"(v) : "f"(lo), "f"(hi));
    return v;
}

// ---------------------------------------------------------------------------
// Precompute ||e_k||^2
// ---------------------------------------------------------------------------
__global__ void ee_kernel(const float* __restrict__ ew) {
    int k = blockIdx.x * blockDim.x + threadIdx.x;
    if (k >= K_) return;
    const float4* r = reinterpret_cast<const float4*>(ew + (size_t)k * C_);
    float4 a = make_float4(0.f, 0.f, 0.f, 0.f);
#pragma unroll
    for (int c4 = 0; c4 < 16; c4++) {
        float4 e = r[c4];
        a.x = fmaf(e.x, e.x, a.x);
        a.y = fmaf(e.y, e.y, a.y);
        a.z = fmaf(e.z, e.z, a.z);
        a.w = fmaf(e.w, e.w, a.w);
    }
    g_ee[k] = (a.x + a.y) + (a.z + a.w);
}

// ---------------------------------------------------------------------------
// Main VQ kernel. One thread per point; codebook tiled through smem.
// 4 codes processed per inner iteration -> 8 independent FFMA2 chains to
// cover the ~5-cycle RAW latency. Per-code rounding identical to the fp32
// reference: lanes (a.x,a.y)/(a.z,a.w), reduce (ax+ay)+(az+aw),
// d = (zz+ee) - 2*dot single-rounded, strict '<' ascending-k argmin.
// ---------------------------------------------------------------------------
__global__ __launch_bounds__(TPB)
void vq_kernel(const float* __restrict__ z, const float* __restrict__ ew,
               float* __restrict__ out, int out_size)
{
    __shared__ __align__(16) float es[TK * C_];   // 32 KB code tile
    __shared__ float see[TK];
    __shared__ float sred[TPB];
    __shared__ int   sidx[TPB];

    const int tid = threadIdx.x;
    const int p0  = blockIdx.x * TPB;
    const int b   = p0 / HW_;
    const int hw0 = p0 - b * HW_;
    const float* zp = z + (size_t)b * CHW_ + (hw0 + tid);

    // Load this thread's point: 64 channels, stride HW_, packed as 32 f32x2.
    unsigned long long zll[32];
#pragma unroll
    for (int c4 = 0; c4 < 16; c4++) {
        float x  = zp[(size_t)(4*c4 + 0) * HW_];
        float y  = zp[(size_t)(4*c4 + 1) * HW_];
        float zc = zp[(size_t)(4*c4 + 2) * HW_];
        float w  = zp[(size_t)(4*c4 + 3) * HW_];
        zll[2*c4]     = pack2(x, y);
        zll[2*c4 + 1] = pack2(zc, w);
    }

    // zz = ||z||^2 (same lane structure)
    unsigned long long az0 = 0ull, az1 = 0ull;
#pragma unroll
    for (int c4 = 0; c4 < 16; c4++) {
        ffma2(az0, zll[2*c4],     zll[2*c4]);
        ffma2(az1, zll[2*c4 + 1], zll[2*c4 + 1]);
    }
    float zx, zy, zz2, zw;
    unpack2(az0, zx, zy);
    unpack2(az1, zz2, zw);
    const float zz = (zx + zy) + (zz2 + zw);

    float best = CUDART_INF_F;
    int   bidx = 0;

    for (int k0 = 0; k0 < K_; k0 += TK) {
        __syncthreads();
#pragma unroll 8
        for (int j = 0; j < (TK * C_) / TPB; j++)
            es[j * TPB + tid] = ew[(size_t)k0 * C_ + j * TPB + tid];
        see[tid] = g_ee[k0 + tid];
        __syncthreads();

        // 4 codes per iteration: 8 independent accumulator chains
        for (int k = 0; k < TK; k += 4) {
            const ulonglong2* er0 = reinterpret_cast<const ulonglong2*>(es + (k+0) * C_);
            const ulonglong2* er1 = reinterpret_cast<const ulonglong2*>(es + (k+1) * C_);
            const ulonglong2* er2 = reinterpret_cast<const ulonglong2*>(es + (k+2) * C_);
            const ulonglong2* er3 = reinterpret_cast<const ulonglong2*>(es + (k+3) * C_);
            unsigned long long a00 = 0ull, a01 = 0ull;
            unsigned long long a10 = 0ull, a11 = 0ull;
            unsigned long long a20 = 0ull, a21 = 0ull;
            unsigned long long a30 = 0ull, a31 = 0ull;
#pragma unroll
            for (int c4 = 0; c4 < 16; c4++) {
                const unsigned long long zlo = zll[2*c4];
                const unsigned long long zhi = zll[2*c4 + 1];
                ulonglong2 e0 = er0[c4];
                ffma2(a00, zlo, e0.x); ffma2(a01, zhi, e0.y);
                ulonglong2 e1 = er1[c4];
                ffma2(a10, zlo, e1.x); ffma2(a11, zhi, e1.y);
                ulonglong2 e2 = er2[c4];
                ffma2(a20, zlo, e2.x); ffma2(a21, zhi, e2.y);
                ulonglong2 e3 = er3[c4];
                ffma2(a30, zlo, e3.x); ffma2(a31, zhi, e3.y);
            }
            float f0, f1, f2, f3, dot, d;
            // code k+0
            unpack2(a00, f0, f1); unpack2(a01, f2, f3);
            dot = (f0 + f1) + (f2 + f3);
            d = fmaf(-2.0f, dot, zz + see[k + 0]);
            if (d < best) { best = d; bidx = k0 + k + 0; }
            // code k+1
            unpack2(a10, f0, f1); unpack2(a11, f2, f3);
            dot = (f0 + f1) + (f2 + f3);
            d = fmaf(-2.0f, dot, zz + see[k + 1]);
            if (d < best) { best = d; bidx = k0 + k + 1; }
            // code k+2
            unpack2(a20, f0, f1); unpack2(a21, f2, f3);
            dot = (f0 + f1) + (f2 + f3);
            d = fmaf(-2.0f, dot, zz + see[k + 2]);
            if (d < best) { best = d; bidx = k0 + k + 2; }
            // code k+3
            unpack2(a30, f0, f1); unpack2(a31, f2, f3);
            dot = (f0 + f1) + (f2 + f3);
            d = fmaf(-2.0f, dot, zz + see[k + 3]);
            if (d < best) { best = d; bidx = k0 + k + 3; }
        }
    }

    sidx[tid] = bidx;

    // Commitment-loss partial: sum_c (e[bidx][c] - z[c])^2
    const float4* erow = reinterpret_cast<const float4*>(ew + (size_t)bidx * C_);
    float4 al = make_float4(0.f, 0.f, 0.f, 0.f);
#pragma unroll
    for (int c4 = 0; c4 < 16; c4++) {
        float4 e = __ldg(erow + c4);
        float l0, l1, l2, l3;
        unpack2(zll[2*c4],     l0, l1);
        unpack2(zll[2*c4 + 1], l2, l3);
        float dx = e.x - l0; al.x = fmaf(dx, dx, al.x);
        float dy = e.y - l1; al.y = fmaf(dy, dy, al.y);
        float dz = e.z - l2; al.z = fmaf(dz, dz, al.z);
        float dw = e.w - l3; al.w = fmaf(dw, dw, al.w);
    }
    sred[tid] = (al.x + al.y) + (al.z + al.w);
    __syncthreads();
#pragma unroll
    for (int s = TPB / 2; s > 0; s >>= 1) {
        if (tid < s) sred[tid] += sred[tid + s];
        __syncthreads();
    }
    if (tid == 0) g_partials[blockIdx.x] = sred[0];

    // Quantized output (straight-through rounding: z + (q - z)), transposed
    // back to (B,C,H,W), coalesced stores.
    const size_t obase = (size_t)b * CHW_ + hw0;
    for (int i = tid; i < TPB * C_; i += TPB) {
        int c = i >> 7;
        int p = i & (TPB - 1);
        float qv = ew[(size_t)sidx[p] * C_ + c];
        size_t gi = obase + (size_t)c * HW_ + p;
        float zv = z[gi];
        out[gi] = zv + (qv - zv);
    }

    if ((long long)out_size >= (long long)NPTS * C_ + NPTS)
        out[(size_t)NPTS * C_ + p0 + tid] = (float)bidx;
}

// ---------------------------------------------------------------------------
// Deterministic final loss reduction
// ---------------------------------------------------------------------------
__global__ void loss_kernel(float* __restrict__ out, int out_size) {
    __shared__ double sd[256];
    int tid = threadIdx.x;
    double s = 0.0;
#pragma unroll
    for (int j = 0; j < NBLK / 256; j++)
        s += (double)g_partials[tid * (NBLK / 256) + j];
    sd[tid] = s;
    __syncthreads();
#pragma unroll
    for (int st = 128; st > 0; st >>= 1) {
        if (tid < st) sd[tid] += sd[tid + st];
        __syncthreads();
    }
    if (tid == 0 && (long long)out_size >= (long long)NPTS * C_ + NPTS + 1)
        out[(size_t)NPTS * C_ + NPTS] =
            (float)(0.25 * sd[0] / (double)((size_t)NPTS * C_));
}

// ---------------------------------------------------------------------------
extern "C" void kernel_launch(void* const* d_in, const int* in_sizes, int n_in,
                              void* d_out, int out_size)
{
    const float* z  = (const float*)d_in[0];   // (32, 64, 64, 64) f32
    const float* ew = (const float*)d_in[1];   // (2048, 64) f32
    float* out = (float*)d_out;

    ee_kernel<<<(K_ + 127) / 128, 128>>>(ew);
    vq_kernel<<<NBLK, TPB>>>(z, ew, out, out_size);
    loss_kernel<<<1, 256>>>(out, out_size);
}

// round 5
// speedup vs baseline: 1.6045x; 1.6045x over previous
#include <cuda_runtime.h>
#include <math_constants.h>

// Problem constants (from reference)
#define B_    32
#define C_    64
#define H_    64
#define W_    64
#define HW_   (H_*W_)          // 4096
#define CHW_  (C_*HW_)         // 262144
#define NPTS  (B_*HW_)         // 131072 points
#define K_    2048             // codebook entries
#define TPB   128              // threads per block
#define PPT   2                // points per thread
#define PPB   (TPB*PPT)        // 256 points per block
#define NBLK  (NPTS/PPB)       // 512 blocks
#define TK    128              // codes per smem tile

// Scratch (no allocations allowed)
__device__ float g_ee[K_];          // ||e_k||^2
__device__ float g_partials[NBLK];  // per-block loss partial sums

// Packed fp32x2 FMA: two independent IEEE fp32 RN FMAs per issue slot (FFMA2).
__device__ __forceinline__ void ffma2(unsigned long long& acc,
                                      unsigned long long a,
                                      unsigned long long b) {
    asm("fma.rn.f32x2 %0, %1, %2, %0;" : "+l"(acc) : "l"(a), "l"(b));
}
__device__ __forceinline__ void unpack2(unsigned long long v, float& lo, float& hi) {
    asm("mov.b64 {%0, %1}, %2;" : "=f"(lo), "=f"(hi) : "l"(v));
}
__device__ __forceinline__ unsigned long long pack2(float lo, float hi) {
    unsigned long long v;
    asm("mov.b64 %0, {%1, %2};" : "=l"(v) : "f"(lo), "f"(hi));
    return v;
}

// ---------------------------------------------------------------------------
// Precompute ||e_k||^2
// ---------------------------------------------------------------------------
__global__ void ee_kernel(const float* __restrict__ ew) {
    int k = blockIdx.x * blockDim.x + threadIdx.x;
    if (k >= K_) return;
    const float4* r = reinterpret_cast<const float4*>(ew + (size_t)k * C_);
    float4 a = make_float4(0.f, 0.f, 0.f, 0.f);
#pragma unroll
    for (int c4 = 0; c4 < 16; c4++) {
        float4 e = r[c4];
        a.x = fmaf(e.x, e.x, a.x);
        a.y = fmaf(e.y, e.y, a.y);
        a.z = fmaf(e.z, e.z, a.z);
        a.w = fmaf(e.w, e.w, a.w);
    }
    g_ee[k] = (a.x + a.y) + (a.z + a.w);
}

// ---------------------------------------------------------------------------
// Main VQ kernel. TWO points per thread: each codebook LDS feeds 4 FFMA2
// (2 points x 2 lane-pairs) -> LDS instruction count per point halved.
// Per-point rounding identical to the fp32 reference: lanes
// (a.x,a.y)/(a.z,a.w), reduce (ax+ay)+(az+aw), d=(zz+ee)-2*dot single-
// rounded, strict '<' ascending-k argmin (first-occurrence tiebreak).
// ---------------------------------------------------------------------------
__global__ __launch_bounds__(TPB, 2)
void vq_kernel(const float* __restrict__ z, const float* __restrict__ ew,
               float* __restrict__ out, int out_size)
{
    __shared__ __align__(16) float es[TK * C_];   // 32 KB code tile
    __shared__ float see[TK];
    __shared__ float sred[TPB];
    __shared__ int   sidx[PPB];

    const int tid = threadIdx.x;
    const int p0  = blockIdx.x * PPB;           // first point of this block
    const int b   = p0 / HW_;
    const int hw0 = p0 - b * HW_;               // 256 consecutive hw positions
    const float* zp = z + (size_t)b * CHW_ + (hw0 + tid);

    // Load two points (A: +tid, B: +tid+128), packed as f32x2 per lane pair.
    unsigned long long zA[32], zB[32];
#pragma unroll
    for (int c4 = 0; c4 < 16; c4++) {
        float a0 = zp[(size_t)(4*c4 + 0) * HW_];
        float a1 = zp[(size_t)(4*c4 + 1) * HW_];
        float a2 = zp[(size_t)(4*c4 + 2) * HW_];
        float a3 = zp[(size_t)(4*c4 + 3) * HW_];
        zA[2*c4]     = pack2(a0, a1);
        zA[2*c4 + 1] = pack2(a2, a3);
        float b0 = zp[(size_t)(4*c4 + 0) * HW_ + TPB];
        float b1 = zp[(size_t)(4*c4 + 1) * HW_ + TPB];
        float b2 = zp[(size_t)(4*c4 + 2) * HW_ + TPB];
        float b3 = zp[(size_t)(4*c4 + 3) * HW_ + TPB];
        zB[2*c4]     = pack2(b0, b1);
        zB[2*c4 + 1] = pack2(b2, b3);
    }

    // zz for both points (same lane structure as reference match)
    float zzA, zzB;
    {
        unsigned long long s0 = 0ull, s1 = 0ull, t0 = 0ull, t1 = 0ull;
#pragma unroll
        for (int c4 = 0; c4 < 16; c4++) {
            ffma2(s0, zA[2*c4],     zA[2*c4]);
            ffma2(s1, zA[2*c4 + 1], zA[2*c4 + 1]);
            ffma2(t0, zB[2*c4],     zB[2*c4]);
            ffma2(t1, zB[2*c4 + 1], zB[2*c4 + 1]);
        }
        float x, y, u, v;
        unpack2(s0, x, y); unpack2(s1, u, v);
        zzA = (x + y) + (u + v);
        unpack2(t0, x, y); unpack2(t1, u, v);
        zzB = (x + y) + (u + v);
    }

    float bestA = CUDART_INF_F, bestB = CUDART_INF_F;
    int   bidxA = 0, bidxB = 0;

    for (int k0 = 0; k0 < K_; k0 += TK) {
        __syncthreads();
#pragma unroll 8
        for (int j = 0; j < (TK * C_) / TPB; j++)
            es[j * TPB + tid] = ew[(size_t)k0 * C_ + j * TPB + tid];
        see[tid] = g_ee[k0 + tid];
        __syncthreads();

        // 2 codes x 2 points per iteration: 8 independent FFMA2 chains,
        // each e-load feeds 4 FFMA2.
        for (int k = 0; k < TK; k += 2) {
            const ulonglong2* er0 = reinterpret_cast<const ulonglong2*>(es + (k+0) * C_);
            const ulonglong2* er1 = reinterpret_cast<const ulonglong2*>(es + (k+1) * C_);
            unsigned long long aA00 = 0ull, aA01 = 0ull, aA10 = 0ull, aA11 = 0ull;
            unsigned long long aB00 = 0ull, aB01 = 0ull, aB10 = 0ull, aB11 = 0ull;
#pragma unroll
            for (int c4 = 0; c4 < 16; c4++) {
                const unsigned long long zAlo = zA[2*c4], zAhi = zA[2*c4 + 1];
                const unsigned long long zBlo = zB[2*c4], zBhi = zB[2*c4 + 1];
                ulonglong2 e0 = er0[c4];   // broadcast LDS.128
                ffma2(aA00, zAlo, e0.x); ffma2(aA01, zAhi, e0.y);
                ffma2(aB00, zBlo, e0.x); ffma2(aB01, zBhi, e0.y);
                ulonglong2 e1 = er1[c4];
                ffma2(aA10, zAlo, e1.x); ffma2(aA11, zAhi, e1.y);
                ffma2(aB10, zBlo, e1.x); ffma2(aB11, zBhi, e1.y);
            }
            float f0, f1, f2, f3, dot, d;
            const float ee0 = see[k], ee1 = see[k + 1];
            // point A, code k
            unpack2(aA00, f0, f1); unpack2(aA01, f2, f3);
            dot = (f0 + f1) + (f2 + f3);
            d = fmaf(-2.0f, dot, zzA + ee0);
            if (d < bestA) { bestA = d; bidxA = k0 + k; }
            // point A, code k+1
            unpack2(aA10, f0, f1); unpack2(aA11, f2, f3);
            dot = (f0 + f1) + (f2 + f3);
            d = fmaf(-2.0f, dot, zzA + ee1);
            if (d < bestA) { bestA = d; bidxA = k0 + k + 1; }
            // point B, code k
            unpack2(aB00, f0, f1); unpack2(aB01, f2, f3);
            dot = (f0 + f1) + (f2 + f3);
            d = fmaf(-2.0f, dot, zzB + ee0);
            if (d < bestB) { bestB = d; bidxB = k0 + k; }
            // point B, code k+1
            unpack2(aB10, f0, f1); unpack2(aB11, f2, f3);
            dot = (f0 + f1) + (f2 + f3);
            d = fmaf(-2.0f, dot, zzB + ee1);
            if (d < bestB) { bestB = d; bidxB = k0 + k + 1; }
        }
    }

    sidx[tid]       = bidxA;
    sidx[tid + TPB] = bidxB;

    // Commitment-loss partials for both points: sum_c (e[bidx][c] - z[c])^2
    float part = 0.f;
    {
        const float4* erow = reinterpret_cast<const float4*>(ew + (size_t)bidxA * C_);
        float4 al = make_float4(0.f, 0.f, 0.f, 0.f);
#pragma unroll
        for (int c4 = 0; c4 < 16; c4++) {
            float4 e = __ldg(erow + c4);
            float l0, l1, l2, l3;
            unpack2(zA[2*c4],     l0, l1);
            unpack2(zA[2*c4 + 1], l2, l3);
            float dx = e.x - l0; al.x = fmaf(dx, dx, al.x);
            float dy = e.y - l1; al.y = fmaf(dy, dy, al.y);
            float dz = e.z - l2; al.z = fmaf(dz, dz, al.z);
            float dw = e.w - l3; al.w = fmaf(dw, dw, al.w);
        }
        part += (al.x + al.y) + (al.z + al.w);
    }
    {
        const float4* erow = reinterpret_cast<const float4*>(ew + (size_t)bidxB * C_);
        float4 al = make_float4(0.f, 0.f, 0.f, 0.f);
#pragma unroll
        for (int c4 = 0; c4 < 16; c4++) {
            float4 e = __ldg(erow + c4);
            float l0, l1, l2, l3;
            unpack2(zB[2*c4],     l0, l1);
            unpack2(zB[2*c4 + 1], l2, l3);
            float dx = e.x - l0; al.x = fmaf(dx, dx, al.x);
            float dy = e.y - l1; al.y = fmaf(dy, dy, al.y);
            float dz = e.z - l2; al.z = fmaf(dz, dz, al.z);
            float dw = e.w - l3; al.w = fmaf(dw, dw, al.w);
        }
        part += (al.x + al.y) + (al.z + al.w);
    }
    sred[tid] = part;
    __syncthreads();                 // also publishes sidx[]
#pragma unroll
    for (int s = TPB / 2; s > 0; s >>= 1) {
        if (tid < s) sred[tid] += sred[tid + s];
        __syncthreads();
    }
    if (tid == 0) g_partials[blockIdx.x] = sred[0];

    // Quantized output (straight-through rounding: z + (q - z)), transposed
    // back to (B,C,H,W), coalesced stores (256 consecutive hw per c, written
    // as two 128-wide groups).
    const size_t obase = (size_t)b * CHW_ + hw0;
    for (int i = tid; i < PPB * C_; i += TPB) {
        int c = i >> 8;              // i / 256
        int p = i & (PPB - 1);       // i % 256
        float qv = ew[(size_t)sidx[p] * C_ + c];
        size_t gi = obase + (size_t)c * HW_ + p;
        float zv = z[gi];
        out[gi] = zv + (qv - zv);
    }

    // Indices output (as float), if the output buffer includes them
    if ((long long)out_size >= (long long)NPTS * C_ + NPTS) {
        out[(size_t)NPTS * C_ + p0 + tid]       = (float)bidxA;
        out[(size_t)NPTS * C_ + p0 + tid + TPB] = (float)bidxB;
    }
}

// ---------------------------------------------------------------------------
// Deterministic final loss reduction
// ---------------------------------------------------------------------------
__global__ void loss_kernel(float* __restrict__ out, int out_size) {
    __shared__ double sd[256];
    int tid = threadIdx.x;
    double s = 0.0;
#pragma unroll
    for (int j = 0; j < NBLK / 256; j++)
        s += (double)g_partials[tid * (NBLK / 256) + j];
    sd[tid] = s;
    __syncthreads();
#pragma unroll
    for (int st = 128; st > 0; st >>= 1) {
        if (tid < st) sd[tid] += sd[tid + st];
        __syncthreads();
    }
    if (tid == 0 && (long long)out_size >= (long long)NPTS * C_ + NPTS + 1)
        out[(size_t)NPTS * C_ + NPTS] =
            (float)(0.25 * sd[0] / (double)((size_t)NPTS * C_));
}

// ---------------------------------------------------------------------------
extern "C" void kernel_launch(void* const* d_in, const int* in_sizes, int n_in,
                              void* d_out, int out_size)
{
    const float* z  = (const float*)d_in[0];   // (32, 64, 64, 64) f32
    const float* ew = (const float*)d_in[1];   // (2048, 64) f32
    float* out = (float*)d_out;

    ee_kernel<<<(K_ + 127) / 128, 128>>>(ew);
    vq_kernel<<<NBLK, TPB>>>(z, ew, out, out_size);
    loss_kernel<<<1, 256>>>(out, out_size);
}